// round 16
// baseline (speedup 1.0000x reference)
#include <cuda_runtime.h>
#include <cstdint>

#define NNODES 50000
#define EEDGES 800000
#define DIN 512
#define DHID 512
#define DOUT 256

// ---------------- static device scratch (no allocations allowed) ----------------
__device__ __align__(16) int8_t g_A8hi[(size_t)NNODES * DIN];
__device__ __align__(16) int8_t g_A8lo[(size_t)NNODES * DIN];
__device__ __align__(16) int8_t g_E8hi[(size_t)NNODES * DHID];
__device__ __align__(16) int8_t g_E8lo[(size_t)NNODES * DHID];
__device__ __align__(16) int8_t g_W18hi[DHID * DIN];
__device__ __align__(16) int8_t g_W18lo[DHID * DIN];
__device__ __align__(16) int8_t g_W28hi[DOUT * DHID];
__device__ __align__(16) int8_t g_W28lo[DOUT * DHID];
__device__ float g_sA[NNODES];
__device__ float g_sE[NNODES];
__device__ float g_sW1[DHID];
__device__ float g_sW2[DOUT];
__device__ float g_T  [(size_t)NNODES * DOUT];   // emb @ W2^T
__device__ float g_emb[(size_t)NNODES * DHID];   // embedding fallback buffer
__device__ int   g_deg[NNODES];                  // zero-init; re-zeroed each call in prop1
__device__ int   g_cursor[NNODES];
__device__ int   g_rowptr[NNODES + 1];
__device__ int   g_colidx[EEDGES];
__device__ float g_dinv[NNODES];
__device__ int   g_is64;

// ---------------- PTX helpers ----------------
__device__ __forceinline__ uint32_t smem_u32(const void* p) {
    uint32_t a;
    asm("{ .reg .u64 t; cvta.to.shared.u64 t, %1; cvt.u32.u64 %0, t; }" : "=r"(a) : "l"(p));
    return a;
}
#define LDX4(r0, r1, r2, r3, addr)                                               \
    asm volatile("ldmatrix.sync.aligned.m8n8.x4.shared.b16 {%0,%1,%2,%3}, [%4];" \
                 : "=r"(r0), "=r"(r1), "=r"(r2), "=r"(r3) : "r"(addr))

__device__ __forceinline__ void imma(int* d, const uint32_t* a, const uint32_t* b) {
    asm volatile(
        "mma.sync.aligned.m16n8k32.row.col.s32.s8.s8.s32 "
        "{%0,%1,%2,%3}, {%4,%5,%6,%7}, {%8,%9}, {%0,%1,%2,%3};"
        : "+r"(d[0]), "+r"(d[1]), "+r"(d[2]), "+r"(d[3])
        : "r"(a[0]), "r"(a[1]), "r"(a[2]), "r"(a[3]), "r"(b[0]), "r"(b[1]));
}

// ---------------- int8 hi/lo quantization helpers ----------------
__device__ __forceinline__ unsigned pack4(int a, int b, int c, int d) {
    return (unsigned)(a & 255) | ((unsigned)(b & 255) << 8) |
           ((unsigned)(c & 255) << 16) | ((unsigned)(d & 255) << 24);
}
__device__ __forceinline__ void quant4(float4 v, float inv, unsigned& phi, unsigned& plo) {
    float q0 = v.x * inv, h0 = rintf(q0);
    float q1 = v.y * inv, h1 = rintf(q1);
    float q2 = v.z * inv, h2 = rintf(q2);
    float q3 = v.w * inv, h3 = rintf(q3);
    phi = pack4((int)h0, (int)h1, (int)h2, (int)h3);
    plo = pack4((int)rintf((q0 - h0) * 128.f), (int)rintf((q1 - h1) * 128.f),
                (int)rintf((q2 - h2) * 128.f), (int)rintf((q3 - h3) * 128.f));
}
__device__ __forceinline__ float warp_absmax16(const float4* acc, int G) {
    float m = 0.f;
    for (int g = 0; g < G; g++) {
        float4 v = acc[g];
        m = fmaxf(m, fmaxf(fmaxf(fabsf(v.x), fabsf(v.y)), fmaxf(fabsf(v.z), fabsf(v.w))));
    }
    #pragma unroll
    for (int o = 16; o > 0; o >>= 1) m = fmaxf(m, __shfl_xor_sync(0xffffffffu, m, o));
    return fmaxf(m, 1e-30f);
}

// ---------------- edge_index dtype probe + safe accessor ----------------
__global__ void k_detect(const unsigned* __restrict__ ei32, int E) {
    int any = 0;
    for (int t = threadIdx.x; t < 1024; t += blockDim.x)
        if (2 * t + 1 < 2 * E && ei32[2 * t + 1] != 0u) any = 1;
    int f = __syncthreads_or(any);
    if (threadIdx.x == 0) g_is64 = f ? 0 : 1;
}
__device__ __forceinline__ int load_idx(const void* ei, int E, int which, int i, int n) {
    long long v;
    if (g_is64) v = ((const long long*)ei)[(size_t)which * E + i];
    else        v = (long long)((const int*)ei)[(size_t)which * E + i];
    if (v < 0) v = 0;
    if (v > n - 1) v = n - 1;
    return (int)v;
}

// ---------------- count edges + quantize W1/W2 (warp per row) ----------------
__global__ void k_countq(const void* __restrict__ ei, int E, int n, int EB,
                         const float* __restrict__ W1, const float* __restrict__ W2) {
    if ((int)blockIdx.x < EB) {
        int i = blockIdx.x * blockDim.x + threadIdx.x;
        if (i < E) {
            int d = load_idx(ei, E, 1, i, n);
            atomicAdd(&g_deg[d], 1);
        }
        return;
    }
    int wr = (blockIdx.x - EB) * 8 + (threadIdx.x >> 5);   // 0..767
    int lane = threadIdx.x & 31;
    if (wr >= DHID + DOUT) return;
    const float* src = (wr < DHID) ? (W1 + (size_t)wr * DIN) : (W2 + (size_t)(wr - DHID) * DHID);
    int8_t* dhi = (wr < DHID) ? (g_W18hi + (size_t)wr * DIN) : (g_W28hi + (size_t)(wr - DHID) * DHID);
    int8_t* dlo = (wr < DHID) ? (g_W18lo + (size_t)wr * DIN) : (g_W28lo + (size_t)(wr - DHID) * DHID);
    float4 v[4];
    #pragma unroll
    for (int g = 0; g < 4; g++) v[g] = ((const float4*)src)[lane + 32 * g];
    float m = warp_absmax16(v, 4);
    float inv = 127.f / m;
    if (lane == 0) {
        if (wr < DHID) g_sW1[wr] = m / 127.f;
        else           g_sW2[wr - DHID] = m / 127.f;
    }
    #pragma unroll
    for (int g = 0; g < 4; g++) {
        unsigned ph, pl;
        quant4(v[g], inv, ph, pl);
        ((unsigned*)dhi)[lane + 32 * g] = ph;
        ((unsigned*)dlo)[lane + 32 * g] = pl;
    }
}

// exclusive scan of g_deg -> g_rowptr (+ fused dinv), single block of 1024
__global__ void k_scandinv(int n) {
    __shared__ int warpsum[32];
    __shared__ int s_carry;
    int tid = threadIdx.x, lane = tid & 31, wid = tid >> 5;
    if (tid == 0) s_carry = 0;
    __syncthreads();
    for (int base = 0; base < n; base += 1024) {
        int i = base + tid;
        int v = (i < n) ? g_deg[i] : 0;
        if (i < n) g_dinv[i] = rsqrtf((float)(v + 1));
        int incl = v;
        #pragma unroll
        for (int off = 1; off < 32; off <<= 1) {
            int t = __shfl_up_sync(0xffffffffu, incl, off);
            if (lane >= off) incl += t;
        }
        if (lane == 31) warpsum[wid] = incl;
        __syncthreads();
        if (wid == 0) {
            int w = warpsum[lane];
            int ws = w;
            #pragma unroll
            for (int off = 1; off < 32; off <<= 1) {
                int t = __shfl_up_sync(0xffffffffu, ws, off);
                if (lane >= off) ws += t;
            }
            warpsum[lane] = ws - w;
        }
        __syncthreads();
        int excl = s_carry + warpsum[wid] + incl - v;
        if (i < n) g_rowptr[i] = excl;
        __syncthreads();
        if (tid == 1023) s_carry += warpsum[31] + incl;
        __syncthreads();
    }
    if (threadIdx.x == 0) g_rowptr[n] = s_carry;
}

__global__ void k_fill(const void* __restrict__ ei, int E, int n) {
    int i = blockIdx.x * blockDim.x + threadIdx.x;
    if (i < E) {
        int s = load_idx(ei, E, 0, i, n);
        int d = load_idx(ei, E, 1, i, n);
        int pos = atomicAdd(&g_cursor[d], 1);
        int slot = g_rowptr[d] + pos;
        if (slot < E) g_colidx[slot] = s;
    }
}

// ---------------- threefry2x32 (partitionable), key = (0, 42); keep <=> bit31(o0^o1)==0 ----
__device__ __forceinline__ float drop_one(unsigned f, float h) {
    const unsigned k0 = 0u, k1 = 42u, k2 = 0x1BD11BDAu ^ k0 ^ k1;
    unsigned x0 = 0u + k0, x1 = f + k1;
#define TFR(r) { x0 += x1; x1 = __funnelshift_l(x1, x1, r); x1 ^= x0; }
    TFR(13) TFR(15) TFR(26) TFR(6)   x0 += k1; x1 += k2 + 1u;
    TFR(17) TFR(29) TFR(16) TFR(24)  x0 += k2; x1 += k0 + 2u;
    TFR(13) TFR(15) TFR(26) TFR(6)   x0 += k0; x1 += k1 + 3u;
    TFR(17) TFR(29) TFR(16) TFR(24)  x0 += k1; x1 += k2 + 4u;
    TFR(13) TFR(15) TFR(26) TFR(6)   x0 += k2; x1 += k0 + 5u;
#undef TFR
    return ((x0 ^ x1) & 0x80000000u) ? 0.f : 2.f * h;
}

// ---------------- propagate: warp-per-node, CSR gather ----------------
// MODE 1: quantize row to A8hi/A8lo + g_sA (no bias). Also re-zeroes deg/cursor.
// MODE 0: fp32 out + bias.
template <int D, int MODE>
__global__ void k_prop(const float* __restrict__ X, float* __restrict__ Y,
                       const float* __restrict__ bias, int n) {
    int t = blockIdx.x * blockDim.x + threadIdx.x;
    if (MODE == 1 && t < n) { g_deg[t] = 0; g_cursor[t] = 0; }   // invariant for next call
    int gw = t >> 5;
    int lane = t & 31;
    if (gw >= n) return;
    const int G = D / 128;

    float di = g_dinv[gw];
    const float4* xs = (const float4*)(X + (size_t)gw * D);
    float4 acc[G];
    float ws = di * di;  // self loop
    #pragma unroll
    for (int g = 0; g < G; g++) {
        float4 v = xs[lane + 32 * g];
        acc[g] = make_float4(ws * v.x, ws * v.y, ws * v.z, ws * v.w);
    }
    int e0 = g_rowptr[gw], e1 = g_rowptr[gw + 1];
    int e = e0;
    for (; e + 1 < e1; e += 2) {
        int j0 = g_colidx[e], j1 = g_colidx[e + 1];
        float w0 = di * g_dinv[j0], w1 = di * g_dinv[j1];
        const float4* x0 = (const float4*)(X + (size_t)j0 * D);
        const float4* x1 = (const float4*)(X + (size_t)j1 * D);
        #pragma unroll
        for (int g = 0; g < G; g++) {
            float4 v0 = x0[lane + 32 * g];
            float4 v1 = x1[lane + 32 * g];
            acc[g].x = fmaf(w0, v0.x, fmaf(w1, v1.x, acc[g].x));
            acc[g].y = fmaf(w0, v0.y, fmaf(w1, v1.y, acc[g].y));
            acc[g].z = fmaf(w0, v0.z, fmaf(w1, v1.z, acc[g].z));
            acc[g].w = fmaf(w0, v0.w, fmaf(w1, v1.w, acc[g].w));
        }
    }
    if (e < e1) {
        int j0 = g_colidx[e];
        float w0 = di * g_dinv[j0];
        const float4* x0 = (const float4*)(X + (size_t)j0 * D);
        #pragma unroll
        for (int g = 0; g < G; g++) {
            float4 v0 = x0[lane + 32 * g];
            acc[g].x = fmaf(w0, v0.x, acc[g].x);
            acc[g].y = fmaf(w0, v0.y, acc[g].y);
            acc[g].z = fmaf(w0, v0.z, acc[g].z);
            acc[g].w = fmaf(w0, v0.w, acc[g].w);
        }
    }
    if (MODE == 1) {
        float m = warp_absmax16(acc, G);
        float inv = 127.f / m;
        if (lane == 0) g_sA[gw] = m / 127.f;
        unsigned* dh = (unsigned*)(g_A8hi + (size_t)gw * D);
        unsigned* dl = (unsigned*)(g_A8lo + (size_t)gw * D);
        #pragma unroll
        for (int g = 0; g < G; g++) {
            unsigned ph, pl;
            quant4(acc[g], inv, ph, pl);
            dh[lane + 32 * g] = ph;
            dl[lane + 32 * g] = pl;
        }
    } else {
        if (bias) {
            const float4* bb = (const float4*)bias;
            #pragma unroll
            for (int g = 0; g < G; g++) {
                float4 b = bb[lane + 32 * g];
                acc[g].x += b.x; acc[g].y += b.y; acc[g].z += b.z; acc[g].w += b.w;
            }
        }
        float4* ys = (float4*)(Y + (size_t)gw * D);
        #pragma unroll
        for (int g = 0; g < G; g++) ys[lane + 32 * g] = acc[g];
    }
}

// ---------------- quantize emb rows (warp per row) for gemm2 ----------------
__global__ void k_equant(const float* __restrict__ emb, int n) {
    int gw = (blockIdx.x * blockDim.x + threadIdx.x) >> 5;
    int lane = threadIdx.x & 31;
    if (gw >= n) return;
    float4 v[4];
    #pragma unroll
    for (int g = 0; g < 4; g++) v[g] = ((const float4*)(emb + (size_t)gw * DHID))[lane + 32 * g];
    float m = warp_absmax16(v, 4);
    float inv = 127.f / m;
    if (lane == 0) g_sE[gw] = m / 127.f;
    unsigned* dh = (unsigned*)(g_E8hi + (size_t)gw * DHID);
    unsigned* dl = (unsigned*)(g_E8lo + (size_t)gw * DHID);
    #pragma unroll
    for (int g = 0; g < 4; g++) {
        unsigned ph, pl;
        quant4(v[g], inv, ph, pl);
        dh[lane + 32 * g] = ph;
        dl[lane + 32 * g] = pl;
    }
}

// ---------------- int8 mma GEMM: C = (sA.sW) * (A8 @ W8^T), hi/lo split, k32 IMMA --------
// CTA 128x128, 512 threads, 16 warps (32x32 warp tiles), K-chunks of 64 s8, double buffer.
// smem tile: 128 rows x 64 s8, row stride 80 B (conflict-free ldmatrix b16-view).
// EPI==1: bias+relu+dropout, fp32 C stride 512.  EPI==0: fp32 C stride ncol.
#define TILE_B 10240
template <int EPI>
__global__ __launch_bounds__(512)
void k_gemm_i8(const int8_t* __restrict__ A8h, const int8_t* __restrict__ A8l,
               const float* __restrict__ sA,
               const int8_t* __restrict__ W8h, const int8_t* __restrict__ W8l,
               const float* __restrict__ sW,
               const float* __restrict__ bias, float* __restrict__ C,
               int nrows, int ncol) {
    extern __shared__ char dsm[];   // 2 stages x 4 arrays x TILE_B = 81920 B
    int tid = threadIdx.x;
    int warp = tid >> 5, lane = tid & 31;
    int br = blockIdx.x, bc = blockIdx.y;
    int m0 = (warp >> 2) * 32;
    int n0 = (warp & 3) * 32;

    // loader: one uint4 (16 s8) per thread per array per chunk
    int lr = tid >> 2;              // row 0..127
    int lc = tid & 3;               // 16-byte slot in the 64B k-chunk row
    long arow = (long)br * 128 + lr; if (arow > nrows - 1) arow = nrows - 1;
    long wrow = (long)bc * 128 + lr;
    const int8_t* srcp[4] = {A8h + arow * 512 + lc * 16, A8l + arow * 512 + lc * 16,
                             W8h + wrow * 512 + lc * 16, W8l + wrow * 512 + lc * 16};
    int soff = lr * 80 + lc * 16;   // byte offset inside a tile

    uint32_t smbase = smem_u32(dsm);

    int accH[2][4][4], accL[2][4][4];
    #pragma unroll
    for (int mt = 0; mt < 2; mt++)
        #pragma unroll
        for (int nt = 0; nt < 4; nt++)
            #pragma unroll
            for (int q = 0; q < 4; q++) { accH[mt][nt][q] = 0; accL[mt][nt][q] = 0; }

    // ldmatrix lane address components (b16-view; 1 b16 = 2 s8)
    int a_r = (lane & 15);
    int a_c16 = (lane >> 4) << 3;
    int b_r = (lane & 7) + ((lane >> 4) << 3);
    int b_c16 = ((lane >> 3) & 1) << 3;

    // prologue: chunk 0 -> stage 0
    {
        uint4 v[4];
        #pragma unroll
        for (int t = 0; t < 4; t++) v[t] = *(const uint4*)srcp[t];
        #pragma unroll
        for (int t = 0; t < 4; t++) *(uint4*)(dsm + t * TILE_B + soff) = v[t];
    }
    __syncthreads();

    #pragma unroll 1
    for (int s = 0; s < 8; s++) {
        uint4 v[4];
        if (s < 7) {
            #pragma unroll
            for (int t = 0; t < 4; t++) v[t] = *(const uint4*)(srcp[t] + (s + 1) * 64);
        }
        uint32_t stb = smbase + (uint32_t)((s & 1) * 4) * TILE_B;
        #pragma unroll
        for (int kk = 0; kk < 2; kk++) {          // two k32 steps per 64-chunk
            int cA = (kk * 16 + a_c16) * 2;       // bytes
            int cB = (kk * 16 + b_c16) * 2;
            uint32_t ah[2][4], al[2][4], bh[4][2], bl[4][2];
            #pragma unroll
            for (int mt = 0; mt < 2; mt++) {
                uint32_t ao = stb + (uint32_t)((m0 + mt * 16 + a_r) * 80 + cA);
                LDX4(ah[mt][0], ah[mt][1], ah[mt][2], ah[mt][3], ao);
                LDX4(al[mt][0], al[mt][1], al[mt][2], al[mt][3], ao + TILE_B);
            }
            #pragma unroll
            for (int ng = 0; ng < 2; ng++) {
                uint32_t bo = stb + 2u * TILE_B
                            + (uint32_t)((n0 + ng * 16 + b_r) * 80 + cB);
                LDX4(bh[2 * ng][0], bh[2 * ng][1], bh[2 * ng + 1][0], bh[2 * ng + 1][1], bo);
                LDX4(bl[2 * ng][0], bl[2 * ng][1], bl[2 * ng + 1][0], bl[2 * ng + 1][1],
                     bo + TILE_B);
            }
            #pragma unroll
            for (int mt = 0; mt < 2; mt++)
                #pragma unroll
                for (int nt = 0; nt < 4; nt++) {
                    imma(accH[mt][nt], ah[mt], bh[nt]);   // HH
                    imma(accL[mt][nt], ah[mt], bl[nt]);   // HL
                    imma(accL[mt][nt], al[mt], bh[nt]);   // LH (same 1/128 weight)
                }
        }
        if (s < 7) {
            char* nb = dsm + ((s + 1) & 1) * 4 * TILE_B;
            #pragma unroll
            for (int t = 0; t < 4; t++) *(uint4*)(nb + t * TILE_B + soff) = v[t];
        }
        __syncthreads();
    }

    // epilogue. D frag: q0,q1 -> row (lane>>2), cols (lane&3)*2,+1 ; q2,q3 -> row +8.
    const float INV128 = 0.0078125f;
    #pragma unroll
    for (int mt = 0; mt < 2; mt++) {
        #pragma unroll
        for (int nt = 0; nt < 4; nt++) {
            int r = br * 128 + m0 + mt * 16 + (lane >> 2);
            int c = bc * 128 + n0 + nt * 8 + (lane & 3) * 2;
            float sw0 = sW[c], sw1 = sW[c + 1];
            #pragma unroll
            for (int h = 0; h < 2; h++) {
                int rr = r + h * 8;
                if (rr >= nrows) continue;
                float sa = sA[rr];
                float v0 = sa * sw0 * ((float)accH[mt][nt][2 * h] +
                                       (float)accL[mt][nt][2 * h] * INV128);
                float v1 = sa * sw1 * ((float)accH[mt][nt][2 * h + 1] +
                                       (float)accL[mt][nt][2 * h + 1] * INV128);
                if (EPI == 1) {
                    float h0 = fmaxf(v0 + bias[c], 0.f);
                    float h1 = fmaxf(v1 + bias[c + 1], 0.f);
                    unsigned f = (unsigned)rr * 512u + (unsigned)c;
                    *(float2*)(C + (size_t)rr * 512 + c) =
                        make_float2(drop_one(f, h0), drop_one(f + 1, h1));
                } else {
                    *(float2*)(C + (size_t)rr * ncol + c) = make_float2(v0, v1);
                }
            }
        }
    }
}

// ---------------- launch ----------------
extern "C" void kernel_launch(void* const* d_in, const int* in_sizes, int n_in,
                              void* d_out, int out_size) {
    const float* x  = (const float*)d_in[0];
    const void*  ei = d_in[1];
    const float* W1 = (const float*)d_in[2];
    const float* b1 = (const float*)d_in[3];
    const float* W2 = (const float*)d_in[4];
    const float* b2 = (const float*)d_in[5];
    int n = in_sizes[0] / DIN;
    int E = in_sizes[1] / 2;
    float* out = (float*)d_out;

    // device scratch addresses (pure queries; capture-safe)
    int8_t *a8h, *a8l, *e8h, *e8l, *w1h, *w1l, *w2h, *w2l;
    float *sa, *se, *sw1, *sw2, *tt, *embg;
    { void* p;
      cudaGetSymbolAddress(&p, g_A8hi);  a8h = (int8_t*)p;
      cudaGetSymbolAddress(&p, g_A8lo);  a8l = (int8_t*)p;
      cudaGetSymbolAddress(&p, g_E8hi);  e8h = (int8_t*)p;
      cudaGetSymbolAddress(&p, g_E8lo);  e8l = (int8_t*)p;
      cudaGetSymbolAddress(&p, g_W18hi); w1h = (int8_t*)p;
      cudaGetSymbolAddress(&p, g_W18lo); w1l = (int8_t*)p;
      cudaGetSymbolAddress(&p, g_W28hi); w2h = (int8_t*)p;
      cudaGetSymbolAddress(&p, g_W28lo); w2l = (int8_t*)p;
      cudaGetSymbolAddress(&p, g_sA);    sa  = (float*)p;
      cudaGetSymbolAddress(&p, g_sE);    se  = (float*)p;
      cudaGetSymbolAddress(&p, g_sW1);   sw1 = (float*)p;
      cudaGetSymbolAddress(&p, g_sW2);   sw2 = (float*)p;
      cudaGetSymbolAddress(&p, g_T);     tt   = (float*)p;
      cudaGetSymbolAddress(&p, g_emb);   embg = (float*)p; }

    int full = (out_size >= n * (DHID + DOUT)) ? 1 : 0;
    float* out2 = out + ((size_t)out_size - (size_t)n * DOUT);
    float* embp = full ? out : embg;

    const int TB = 256;
    const int SMEM = 8 * TILE_B;   // 81920 B
    cudaFuncSetAttribute(k_gemm_i8<1>, cudaFuncAttributeMaxDynamicSharedMemorySize, SMEM);
    cudaFuncSetAttribute(k_gemm_i8<0>, cudaFuncAttributeMaxDynamicSharedMemorySize, SMEM);

    int EB = (E + TB - 1) / TB;
    int nb = (n + 127) / 128;

    // setup (deg/cursor arrive zeroed: zero-init at load, re-zeroed in prop1 each call)
    k_detect  <<<1, TB>>>((const unsigned*)ei, E);
    k_countq  <<<EB + 96, TB>>>(ei, E, n, EB, W1, W2);
    k_scandinv<<<1, 1024>>>(n);
    k_fill    <<<EB, TB>>>(ei, E, n);

    // layer 1: P1 = A_hat x (quantized to int8 hi/lo in epilogue)
    k_prop<DIN, 1><<<((long)n * 32 + TB - 1) / TB, TB>>>(x, nullptr, nullptr, n);
    // emb = dropout(relu(P1 @ W1^T + b1))
    k_gemm_i8<1><<<dim3(nb, DHID / 128), 512, SMEM>>>(a8h, a8l, sa, w1h, w1l, sw1,
                                                      b1, embp, n, DHID);
    // quantize emb rows for layer 2
    k_equant<<<((long)n * 32 + TB - 1) / TB, TB>>>(embp, n);
    // layer 2: T = emb @ W2^T ; out = A_hat T + b2   (propagate/linear commute)
    k_gemm_i8<0><<<dim3(nb, DOUT / 128), 512, SMEM>>>(e8h, e8l, se, w2h, w2l, sw2,
                                                      nullptr, tt, n, DOUT);
    k_prop<DOUT, 0><<<((long)n * 32 + TB - 1) / TB, TB>>>(tt, out2, b2, n);
}

// round 17
// speedup vs baseline: 1.8781x; 1.8781x over previous
#include <cuda_runtime.h>
#include <cuda_bf16.h>
#include <cstdint>

#define NNODES 50000
#define EEDGES 800000
#define DIN 512
#define DHID 512
#define DOUT 256

// ---------------- static device scratch (no allocations allowed) ----------------
__device__ __nv_bfloat16 g_Ahi[(size_t)NNODES * DIN];   // P1 hi
__device__ __nv_bfloat16 g_Alo[(size_t)NNODES * DIN];   // P1 lo
__device__ __nv_bfloat16 g_Ehi[(size_t)NNODES * DHID];  // emb hi
__device__ __nv_bfloat16 g_Elo[(size_t)NNODES * DHID];  // emb lo
__device__ __nv_bfloat16 g_W1hi[DHID * DIN];
__device__ __nv_bfloat16 g_W1lo[DHID * DIN];
__device__ __nv_bfloat16 g_W2hi[DOUT * DHID];
__device__ __nv_bfloat16 g_W2lo[DOUT * DHID];
__device__ float g_T  [(size_t)NNODES * DOUT];   // emb @ W2^T
__device__ float g_emb[(size_t)NNODES * DHID];   // embedding fallback buffer
__device__ int   g_deg[NNODES];                  // zero-init; re-zeroed each call in prop1
__device__ int   g_cursor[NNODES];
__device__ int   g_rowptr[NNODES + 1];
__device__ int   g_colidx[EEDGES];
__device__ float g_dinv[NNODES];
__device__ int   g_is64;

// ---------------- PTX helpers ----------------
__device__ __forceinline__ uint32_t smem_u32(const void* p) {
    uint32_t a;
    asm("{ .reg .u64 t; cvta.to.shared.u64 t, %1; cvt.u32.u64 %0, t; }" : "=r"(a) : "l"(p));
    return a;
}
#define LDX4(r0, r1, r2, r3, addr)                                               \
    asm volatile("ldmatrix.sync.aligned.m8n8.x4.shared.b16 {%0,%1,%2,%3}, [%4];" \
                 : "=r"(r0), "=r"(r1), "=r"(r2), "=r"(r3) : "r"(addr))
#define CPA(dst, src)                                                            \
    asm volatile("cp.async.cg.shared.global [%0], [%1], 16;" :: "r"(dst), "l"(src))
#define CPCOMMIT() asm volatile("cp.async.commit_group;" ::: "memory")

__device__ __forceinline__ void mma16816(float* d, const uint32_t* a, const uint32_t* b) {
    asm volatile(
        "mma.sync.aligned.m16n8k16.row.col.f32.bf16.bf16.f32 "
        "{%0,%1,%2,%3}, {%4,%5,%6,%7}, {%8,%9}, {%0,%1,%2,%3};"
        : "+f"(d[0]), "+f"(d[1]), "+f"(d[2]), "+f"(d[3])
        : "r"(a[0]), "r"(a[1]), "r"(a[2]), "r"(a[3]), "r"(b[0]), "r"(b[1]));
}

// ---------------- edge_index accessor (dtype probed into g_is64) ----------------
__device__ __forceinline__ int load_idx(const void* ei, int E, int which, int i, int n) {
    long long v;
    if (g_is64) v = ((const long long*)ei)[(size_t)which * E + i];
    else        v = (long long)((const int*)ei)[(size_t)which * E + i];
    if (v < 0) v = 0;
    if (v > n - 1) v = n - 1;
    return (int)v;
}

__device__ __forceinline__ unsigned pkbf(float a, float b) {
    __nv_bfloat162 t = __floats2bfloat162_rn(a, b);
    return *(unsigned*)&t;
}

// ---------------- setup: edge count (+ local dtype probe) + W hi/lo convert ----------
__global__ void k_countcvt(const void* __restrict__ ei, int E, int n, int EB,
                           const float* __restrict__ W1, const float* __restrict__ W2) {
    if ((int)blockIdx.x < EB) {
        // per-block dtype probe: true int64 (< 2^31) => all odd 32-bit words zero
        const unsigned* e32 = (const unsigned*)ei;
        int any = 0;
        for (int t = threadIdx.x; t < 1024; t += blockDim.x)
            if (2 * t + 1 < 2 * E && e32[2 * t + 1] != 0u) any = 1;
        int found = __syncthreads_or(any);
        int is64 = found ? 0 : 1;
        if (blockIdx.x == 0 && threadIdx.x == 0) g_is64 = is64;   // for later kernels
        int i = blockIdx.x * blockDim.x + threadIdx.x;
        if (i < E) {
            long long v = is64 ? ((const long long*)ei)[(size_t)E + i]
                               : (long long)((const int*)ei)[(size_t)E + i];
            if (v < 0) v = 0;
            if (v > n - 1) v = n - 1;
            atomicAdd(&g_deg[(int)v], 1);
        }
    } else {
        int j = (blockIdx.x - EB) * blockDim.x + threadIdx.x;
        const int W1N = DHID * DIN;
        if (j < W1N) {
            float v = W1[j];
            __nv_bfloat16 h = __float2bfloat16(v);
            g_W1hi[j] = h;
            g_W1lo[j] = __float2bfloat16(v - __bfloat162float(h));
        } else if (j < W1N + DOUT * DHID) {
            int q = j - W1N;
            float v = W2[q];
            __nv_bfloat16 h = __float2bfloat16(v);
            g_W2hi[q] = h;
            g_W2lo[q] = __float2bfloat16(v - __bfloat162float(h));
        }
    }
}

// exclusive scan of g_deg -> g_rowptr (+ fused dinv), single block of 1024
__global__ void k_scandinv(int n) {
    __shared__ int warpsum[32];
    __shared__ int s_carry;
    int tid = threadIdx.x, lane = tid & 31, wid = tid >> 5;
    if (tid == 0) s_carry = 0;
    __syncthreads();
    for (int base = 0; base < n; base += 1024) {
        int i = base + tid;
        int v = (i < n) ? g_deg[i] : 0;
        if (i < n) g_dinv[i] = rsqrtf((float)(v + 1));
        int incl = v;
        #pragma unroll
        for (int off = 1; off < 32; off <<= 1) {
            int t = __shfl_up_sync(0xffffffffu, incl, off);
            if (lane >= off) incl += t;
        }
        if (lane == 31) warpsum[wid] = incl;
        __syncthreads();
        if (wid == 0) {
            int w = warpsum[lane];
            int ws = w;
            #pragma unroll
            for (int off = 1; off < 32; off <<= 1) {
                int t = __shfl_up_sync(0xffffffffu, ws, off);
                if (lane >= off) ws += t;
            }
            warpsum[lane] = ws - w;
        }
        __syncthreads();
        int excl = s_carry + warpsum[wid] + incl - v;
        if (i < n) g_rowptr[i] = excl;
        __syncthreads();
        if (tid == 1023) s_carry += warpsum[31] + incl;
        __syncthreads();
    }
    if (threadIdx.x == 0) g_rowptr[n] = s_carry;
}

__global__ void k_fill(const void* __restrict__ ei, int E, int n) {
    int i = blockIdx.x * blockDim.x + threadIdx.x;
    if (i < E) {
        int s = load_idx(ei, E, 0, i, n);
        int d = load_idx(ei, E, 1, i, n);
        int pos = atomicAdd(&g_cursor[d], 1);
        int slot = g_rowptr[d] + pos;
        if (slot < E) g_colidx[slot] = s;
    }
}

// ---------------- threefry2x32 (partitionable), key = (0, 42); keep <=> bit31(o0^o1)==0 ----
__device__ __forceinline__ float drop_one(unsigned f, float h) {
    const unsigned k0 = 0u, k1 = 42u, k2 = 0x1BD11BDAu ^ k0 ^ k1;
    unsigned x0 = 0u + k0, x1 = f + k1;
#define TFR(r) { x0 += x1; x1 = __funnelshift_l(x1, x1, r); x1 ^= x0; }
    TFR(13) TFR(15) TFR(26) TFR(6)   x0 += k1; x1 += k2 + 1u;
    TFR(17) TFR(29) TFR(16) TFR(24)  x0 += k2; x1 += k0 + 2u;
    TFR(13) TFR(15) TFR(26) TFR(6)   x0 += k0; x1 += k1 + 3u;
    TFR(17) TFR(29) TFR(16) TFR(24)  x0 += k1; x1 += k2 + 4u;
    TFR(13) TFR(15) TFR(26) TFR(6)   x0 += k2; x1 += k0 + 5u;
#undef TFR
    return ((x0 ^ x1) & 0x80000000u) ? 0.f : 2.f * h;
}

// ---------------- propagate: warp-per-node, CSR gather ----------------
// MODE 1: write bf16 hi/lo (g_Ahi/g_Alo), re-zero deg/cursor for next call.
// MODE 0: fp32 out + bias.
template <int D, int MODE>
__global__ void k_prop(const float* __restrict__ X, float* __restrict__ Y,
                       const float* __restrict__ bias, int n) {
    int t = blockIdx.x * blockDim.x + threadIdx.x;
    if (MODE == 1 && t < n) { g_deg[t] = 0; g_cursor[t] = 0; }   // invariant for next call
    int gw = t >> 5;
    int lane = t & 31;
    if (gw >= n) return;
    const int G = D / 128;

    float di = g_dinv[gw];
    const float4* xs = (const float4*)(X + (size_t)gw * D);
    float4 acc[G];
    float ws = di * di;  // self loop
    #pragma unroll
    for (int g = 0; g < G; g++) {
        float4 v = xs[lane + 32 * g];
        acc[g] = make_float4(ws * v.x, ws * v.y, ws * v.z, ws * v.w);
    }
    int e0 = g_rowptr[gw], e1 = g_rowptr[gw + 1];
    int e = e0;
    for (; e + 1 < e1; e += 2) {
        int j0 = g_colidx[e], j1 = g_colidx[e + 1];
        float w0 = di * g_dinv[j0], w1 = di * g_dinv[j1];
        const float4* x0 = (const float4*)(X + (size_t)j0 * D);
        const float4* x1 = (const float4*)(X + (size_t)j1 * D);
        #pragma unroll
        for (int g = 0; g < G; g++) {
            float4 v0 = x0[lane + 32 * g];
            float4 v1 = x1[lane + 32 * g];
            acc[g].x = fmaf(w0, v0.x, fmaf(w1, v1.x, acc[g].x));
            acc[g].y = fmaf(w0, v0.y, fmaf(w1, v1.y, acc[g].y));
            acc[g].z = fmaf(w0, v0.z, fmaf(w1, v1.z, acc[g].z));
            acc[g].w = fmaf(w0, v0.w, fmaf(w1, v1.w, acc[g].w));
        }
    }
    if (e < e1) {
        int j0 = g_colidx[e];
        float w0 = di * g_dinv[j0];
        const float4* x0 = (const float4*)(X + (size_t)j0 * D);
        #pragma unroll
        for (int g = 0; g < G; g++) {
            float4 v0 = x0[lane + 32 * g];
            acc[g].x = fmaf(w0, v0.x, acc[g].x);
            acc[g].y = fmaf(w0, v0.y, acc[g].y);
            acc[g].z = fmaf(w0, v0.z, acc[g].z);
            acc[g].w = fmaf(w0, v0.w, acc[g].w);
        }
    }
    if (MODE == 1) {
        uint2* yh = (uint2*)(g_Ahi + (size_t)gw * D);
        uint2* yl = (uint2*)(g_Alo + (size_t)gw * D);
        #pragma unroll
        for (int g = 0; g < G; g++) {
            float4 v = acc[g];
            __nv_bfloat16 hx = __float2bfloat16(v.x), hy = __float2bfloat16(v.y);
            __nv_bfloat16 hz = __float2bfloat16(v.z), hw = __float2bfloat16(v.w);
            unsigned hi01 = ((unsigned)__bfloat16_as_ushort(hy) << 16) | __bfloat16_as_ushort(hx);
            unsigned hi23 = ((unsigned)__bfloat16_as_ushort(hw) << 16) | __bfloat16_as_ushort(hz);
            yh[lane + 32 * g] = make_uint2(hi01, hi23);
            unsigned lo01 = pkbf(v.x - __bfloat162float(hx), v.y - __bfloat162float(hy));
            unsigned lo23 = pkbf(v.z - __bfloat162float(hz), v.w - __bfloat162float(hw));
            yl[lane + 32 * g] = make_uint2(lo01, lo23);
        }
    } else {
        if (bias) {
            const float4* bb = (const float4*)bias;
            #pragma unroll
            for (int g = 0; g < G; g++) {
                float4 b = bb[lane + 32 * g];
                acc[g].x += b.x; acc[g].y += b.y; acc[g].z += b.z; acc[g].w += b.w;
            }
        }
        float4* ys = (float4*)(Y + (size_t)gw * D);
        #pragma unroll
        for (int g = 0; g < G; g++) ys[lane + 32 * g] = acc[g];
    }
}

// ---------------- mma.sync GEMM v3: bf16 hi/lo 3-term, cp.async pipeline --------
// CTA 128x128, 256 threads (8 warps, 32x64 warp tiles), K stages of 32, 2-stage
// cp.async double buffer, 2 CTAs/SM. smem row stride 80 B (conflict-free ldmatrix).
// EPI==1: bias+relu+dropout -> fp32 C (stride 512) + bf16 hi/lo (Ehi/Elo).
// EPI==0: plain fp32 C (stride ncol).
#define STRB 80
#define TILE_B 10240
template <int EPI>
__global__ __launch_bounds__(256, 2)
void k_gemm_bf(const __nv_bfloat16* __restrict__ Ahi, const __nv_bfloat16* __restrict__ Alo,
               const __nv_bfloat16* __restrict__ Whi, const __nv_bfloat16* __restrict__ Wlo,
               const float* __restrict__ bias, float* __restrict__ C,
               __nv_bfloat16* __restrict__ Ehi, __nv_bfloat16* __restrict__ Elo,
               int nrows, int ncol) {
    extern __shared__ char dsm[];   // 2 stages x 4 arrays x TILE_B = 81920 B
    int tid = threadIdx.x;
    int warp = tid >> 5, lane = tid & 31;
    int br = blockIdx.x, bc = blockIdx.y;
    int m0 = (warp >> 1) * 32;      // 4 m-warps
    int n0 = (warp & 1) * 64;       // 2 n-warps

    uint32_t smbase = smem_u32(dsm);

    // loader: each thread owns rows (r0, r0+64) x 16B slot lc, for all 4 arrays
    int r0 = tid >> 2;
    int lc = tid & 3;
    long ar0 = (long)br * 128 + r0;      if (ar0 > nrows - 1) ar0 = nrows - 1;
    long ar1 = (long)br * 128 + r0 + 64; if (ar1 > nrows - 1) ar1 = nrows - 1;
    long wr0 = (long)bc * 128 + r0;
    long wr1 = wr0 + 64;
    const char* gsrc[8] = {
        (const char*)(Ahi + ar0 * 512 + lc * 8), (const char*)(Ahi + ar1 * 512 + lc * 8),
        (const char*)(Alo + ar0 * 512 + lc * 8), (const char*)(Alo + ar1 * 512 + lc * 8),
        (const char*)(Whi + wr0 * 512 + lc * 8), (const char*)(Whi + wr1 * 512 + lc * 8),
        (const char*)(Wlo + wr0 * 512 + lc * 8), (const char*)(Wlo + wr1 * 512 + lc * 8)};
    uint32_t sdst[8];
    #pragma unroll
    for (int q = 0; q < 8; q++)
        sdst[q] = smbase + (uint32_t)((q >> 1) * TILE_B + (r0 + (q & 1) * 64) * STRB + lc * 16);

    float acc[2][8][4];
    #pragma unroll
    for (int mt = 0; mt < 2; mt++)
        #pragma unroll
        for (int nt = 0; nt < 8; nt++)
            #pragma unroll
            for (int q = 0; q < 4; q++) acc[mt][nt][q] = 0.f;

    // ldmatrix lane address components (bf16 units)
    int a_r = lane & 15;
    int a_c = (lane >> 4) << 3;
    int b_r = (lane & 7) + ((lane >> 4) << 3);
    int b_c = ((lane >> 3) & 1) << 3;

    // prologue: stage 0
    {
        #pragma unroll
        for (int q = 0; q < 8; q++) CPA(sdst[q], gsrc[q]);
        CPCOMMIT();
    }

    #pragma unroll 1
    for (int s = 0; s < 16; s++) {
        if (s < 15) {
            uint32_t bofs = (uint32_t)(((s + 1) & 1) * 4 * TILE_B);
            uint32_t gofs = (uint32_t)(s + 1) * 64;   // 32 bf16 per stage
            #pragma unroll
            for (int q = 0; q < 8; q++) CPA(sdst[q] + bofs, gsrc[q] + gofs);
            CPCOMMIT();
            asm volatile("cp.async.wait_group 1;" ::: "memory");
        } else {
            asm volatile("cp.async.wait_group 0;" ::: "memory");
        }
        __syncthreads();
        uint32_t stb = smbase + (uint32_t)((s & 1) * 4 * TILE_B);
        #pragma unroll
        for (int kk = 0; kk < 32; kk += 16) {
            uint32_t ah[2][4], al[2][4];
            #pragma unroll
            for (int mt = 0; mt < 2; mt++) {
                uint32_t ao = stb + (uint32_t)(((m0 + mt * 16 + a_r) * 40 + kk + a_c) * 2);
                LDX4(ah[mt][0], ah[mt][1], ah[mt][2], ah[mt][3], ao);
                LDX4(al[mt][0], al[mt][1], al[mt][2], al[mt][3], ao + TILE_B);
            }
            #pragma unroll
            for (int ng = 0; ng < 4; ng++) {
                uint32_t bh[2][2], bl[2][2];
                uint32_t bo = stb + 2u * TILE_B
                            + (uint32_t)(((n0 + ng * 16 + b_r) * 40 + kk + b_c) * 2);
                LDX4(bh[0][0], bh[0][1], bh[1][0], bh[1][1], bo);
                LDX4(bl[0][0], bl[0][1], bl[1][0], bl[1][1], bo + TILE_B);
                #pragma unroll
                for (int mt = 0; mt < 2; mt++)
                    #pragma unroll
                    for (int j = 0; j < 2; j++) {
                        mma16816(acc[mt][2 * ng + j], ah[mt], bh[j]);
                        mma16816(acc[mt][2 * ng + j], ah[mt], bl[j]);
                        mma16816(acc[mt][2 * ng + j], al[mt], bh[j]);
                    }
            }
        }
        __syncthreads();   // all warps done reading buf[s&1] before it is refilled
    }

    // epilogue. D frag: q0,q1 -> row (lane>>2), cols (lane&3)*2,+1 ; q2,q3 -> row +8.
    #pragma unroll
    for (int mt = 0; mt < 2; mt++) {
        #pragma unroll
        for (int nt = 0; nt < 8; nt++) {
            int r = br * 128 + m0 + mt * 16 + (lane >> 2);
            int c = bc * 128 + n0 + nt * 8 + (lane & 3) * 2;
            #pragma unroll
            for (int h = 0; h < 2; h++) {
                int rr = r + h * 8;
                if (rr >= nrows) continue;
                float v0 = acc[mt][nt][2 * h], v1 = acc[mt][nt][2 * h + 1];
                if (EPI == 1) {
                    float h0 = fmaxf(v0 + bias[c], 0.f);
                    float h1 = fmaxf(v1 + bias[c + 1], 0.f);
                    unsigned f = (unsigned)rr * 512u + (unsigned)c;
                    float o0 = drop_one(f, h0);
                    float o1 = drop_one(f + 1, h1);
                    *(float2*)(C + (size_t)rr * 512 + c) = make_float2(o0, o1);
                    __nv_bfloat16 e0 = __float2bfloat16(o0), e1 = __float2bfloat16(o1);
                    unsigned hi = ((unsigned)__bfloat16_as_ushort(e1) << 16)
                                | __bfloat16_as_ushort(e0);
                    *(unsigned*)(Ehi + (size_t)rr * 512 + c) = hi;
                    *(unsigned*)(Elo + (size_t)rr * 512 + c) =
                        pkbf(o0 - __bfloat162float(e0), o1 - __bfloat162float(e1));
                } else {
                    *(float2*)(C + (size_t)rr * ncol + c) = make_float2(v0, v1);
                }
            }
        }
    }
}

// ---------------- launch ----------------
extern "C" void kernel_launch(void* const* d_in, const int* in_sizes, int n_in,
                              void* d_out, int out_size) {
    const float* x  = (const float*)d_in[0];
    const void*  ei = d_in[1];
    const float* W1 = (const float*)d_in[2];
    const float* b1 = (const float*)d_in[3];
    const float* W2 = (const float*)d_in[4];
    const float* b2 = (const float*)d_in[5];
    int n = in_sizes[0] / DIN;
    int E = in_sizes[1] / 2;
    float* out = (float*)d_out;

    // device scratch addresses (pure queries; capture-safe)
    __nv_bfloat16 *ahi, *alo, *ehi, *elo, *w1h, *w1l, *w2h, *w2l;
    float *tt, *embg;
    { void* p;
      cudaGetSymbolAddress(&p, g_Ahi);  ahi = (__nv_bfloat16*)p;
      cudaGetSymbolAddress(&p, g_Alo);  alo = (__nv_bfloat16*)p;
      cudaGetSymbolAddress(&p, g_Ehi);  ehi = (__nv_bfloat16*)p;
      cudaGetSymbolAddress(&p, g_Elo);  elo = (__nv_bfloat16*)p;
      cudaGetSymbolAddress(&p, g_W1hi); w1h = (__nv_bfloat16*)p;
      cudaGetSymbolAddress(&p, g_W1lo); w1l = (__nv_bfloat16*)p;
      cudaGetSymbolAddress(&p, g_W2hi); w2h = (__nv_bfloat16*)p;
      cudaGetSymbolAddress(&p, g_W2lo); w2l = (__nv_bfloat16*)p;
      cudaGetSymbolAddress(&p, g_T);    tt   = (float*)p;
      cudaGetSymbolAddress(&p, g_emb);  embg = (float*)p; }

    int full = (out_size >= n * (DHID + DOUT)) ? 1 : 0;
    float* out2 = out + ((size_t)out_size - (size_t)n * DOUT);
    float* embp = full ? out : embg;

    const int TB = 256;
    const int SMEM = 8 * TILE_B;   // 81920 B
    cudaFuncSetAttribute(k_gemm_bf<1>, cudaFuncAttributeMaxDynamicSharedMemorySize, SMEM);
    cudaFuncSetAttribute(k_gemm_bf<0>, cudaFuncAttributeMaxDynamicSharedMemorySize, SMEM);

    int EB = (E + TB - 1) / TB;
    int WB = (DHID * DIN + DOUT * DHID + TB - 1) / TB;
    int nb = (n + 127) / 128;

    // my launches: 1 countcvt, 2 scandinv, 3 fill, 4 prop1 (ncu -s 5 target), 5 gemm1, ...
    k_countcvt<<<EB + WB, TB>>>(ei, E, n, EB, W1, W2);
    k_scandinv<<<1, 1024>>>(n);
    k_fill    <<<EB, TB>>>(ei, E, n);
    k_prop<DIN, 1><<<((long)n * 32 + TB - 1) / TB, TB>>>(x, nullptr, nullptr, n);

    // layer 1: emb = dropout(relu(P1 @ W1^T + b1)); emb also emitted as bf16 hi/lo
    k_gemm_bf<1><<<dim3(nb, DHID / 128), 256, SMEM>>>(ahi, alo, w1h, w1l, b1,
                                                      embp, ehi, elo, n, DHID);
    // layer 2: T = emb @ W2^T ; out = A_hat T + b2   (propagate/linear commute)
    k_gemm_bf<0><<<dim3(nb, DOUT / 128), 256, SMEM>>>(ehi, elo, w2h, w2l, nullptr,
                                                      tt, nullptr, nullptr, n, DOUT);
    k_prop<DOUT, 0><<<((long)n * 32 + TB - 1) / TB, TB>>>(tt, out2, b2, n);
}